// round 1
// baseline (speedup 1.0000x reference)
#include <cuda_runtime.h>
#include <cstdint>

#define NB 8
#define NA 49104
#define NM 50
#define NK 80
#define TPB 256
#define BPI ((NA + TPB - 1) / TPB)   // 192 blocks per image

__device__ float g_cls_sum[NB];
__device__ float g_reg_sum[NB];
__device__ int   g_pos_cnt[NB];

__global__ void zero_kernel() {
    int t = threadIdx.x;
    if (t < NB) { g_cls_sum[t] = 0.f; g_reg_sum[t] = 0.f; g_pos_cnt[t] = 0; }
}

__device__ __forceinline__ float smooth_l1(float d) {
    d = fabsf(d);
    const float BETA = 1.0f / 9.0f;
    return (d <= BETA) ? (0.5f * d * d / BETA) : (d - 0.5f * BETA);
}

__global__ __launch_bounds__(TPB, 4)
void retina_main_kernel(const float* __restrict__ logits,
                        const float* __restrict__ regp,
                        const float* __restrict__ anchors,
                        const float* __restrict__ boxes,
                        const int*   __restrict__ classes)
{
    __shared__ float4 sbox[NM];
    __shared__ float  sarea[NM];
    __shared__ int    scls[NM];
    __shared__ unsigned char sstate[TPB];  // 0=ignore, 1=neg, 2=pos
    __shared__ short  stcls[TPB];
    __shared__ float  sredf[8];
    __shared__ float  sredr[8];
    __shared__ int    sredi[8];

    const int b   = blockIdx.y;
    const int a0  = blockIdx.x * TPB;
    const int tid = threadIdx.x;

    if (tid < NM) {
        float4 bx = ((const float4*)boxes)[b * NM + tid];
        sbox[tid]  = bx;
        sarea[tid] = (bx.z - bx.x) * (bx.w - bx.y);
        scls[tid]  = classes[b * NM + tid];
    }
    sstate[tid] = 0;
    __syncthreads();

    // ---------- phase 1: IoU argmax + regression loss ----------
    const int a = a0 + tid;
    float reg_partial = 0.f;
    int   pos_partial = 0;

    if (a < NA) {
        float4 an = ((const float4*)anchors)[a];
        float areaA = (an.z - an.x) * (an.w - an.y);
        float best = -1e30f;
        int   bi = 0;
        #pragma unroll 10
        for (int j = 0; j < NM; j++) {
            float4 bx = sbox[j];
            float iw = fminf(an.z, bx.z) - fmaxf(an.x, bx.x);
            float ih = fminf(an.w, bx.w) - fmaxf(an.y, bx.y);
            iw = fmaxf(iw, 0.f); ih = fmaxf(ih, 0.f);
            float inter = iw * ih;
            float ua = fmaxf(areaA + sarea[j] - inter, 1e-8f);
            float iou = inter / ua;
            if (bx.x == -1.0f) iou = -1.0f;        // padded box
            if (iou > best) { best = iou; bi = j; }
        }
        bool pos = best >= 0.5f;
        bool neg = best <  0.4f;
        sstate[tid] = pos ? (unsigned char)2 : (neg ? (unsigned char)1 : (unsigned char)0);
        stcls[tid]  = (short)(scls[bi] - 1);

        if (pos) {
            pos_partial = 1;
            float4 gb = sbox[bi];
            float aw = an.z - an.x, ah = an.w - an.y;
            float acx = an.x + 0.5f * aw, acy = an.y + 0.5f * ah;
            float gw0 = gb.z - gb.x, gh0 = gb.w - gb.y;
            float gcx = gb.x + 0.5f * gw0, gcy = gb.y + 0.5f * gh0;
            float gw = fmaxf(gw0, 1.f), gh = fmaxf(gh0, 1.f);
            float t0 = ((gcx - acx) / aw) / 0.1f;
            float t1 = ((gcy - acy) / ah) / 0.1f;
            float t2 = __logf(gw / aw) / 0.2f;
            float t3 = __logf(gh / ah) / 0.2f;
            float4 rp = ((const float4*)regp)[(size_t)b * NA + a];
            reg_partial = smooth_l1(t0 - rp.x) + smooth_l1(t1 - rp.y)
                        + smooth_l1(t2 - rp.z) + smooth_l1(t3 - rp.w);
        }
    }
    __syncthreads();

    // ---------- phase 2: focal loss, coalesced float4 stream ----------
    const int na = min(TPB, NA - a0);
    const int count = na * NK;
    const float* lg = logits + ((size_t)b * NA + a0) * NK;
    float cls_partial = 0.f;

    for (int i4 = tid * 4; i4 < count; i4 += TPB * 4) {
        float4 p4 = *(const float4*)(lg + i4);
        int al = i4 / NK;                 // 80 | i4 groups -> same anchor for all 4
        unsigned char st = sstate[al];
        if (st) {
            int c0 = i4 - al * NK;
            int tc = (st == 2) ? (int)stcls[al] : -1;
            float pv[4] = {p4.x, p4.y, p4.z, p4.w};
            #pragma unroll
            for (int k = 0; k < 4; k++) {
                float p = fminf(fmaxf(pv[k], 1e-4f), 1.f - 1e-4f);
                if (c0 + k == tc)
                    cls_partial += 0.25f * (1.f - p) * (1.f - p) * (-__logf(p));
                else
                    cls_partial += 0.75f * p * p * (-__logf(1.f - p));
            }
        }
    }

    // ---------- reduction ----------
    float cv = cls_partial, rv = reg_partial;
    int   pv = pos_partial;
    #pragma unroll
    for (int off = 16; off > 0; off >>= 1) {
        cv += __shfl_down_sync(0xffffffffu, cv, off);
        rv += __shfl_down_sync(0xffffffffu, rv, off);
        pv += __shfl_down_sync(0xffffffffu, pv, off);
    }
    int wid = tid >> 5, lid = tid & 31;
    if (lid == 0) { sredf[wid] = cv; sredr[wid] = rv; sredi[wid] = pv; }
    __syncthreads();
    if (wid == 0) {
        cv = (lid < 8) ? sredf[lid] : 0.f;
        rv = (lid < 8) ? sredr[lid] : 0.f;
        pv = (lid < 8) ? sredi[lid] : 0;
        #pragma unroll
        for (int off = 4; off > 0; off >>= 1) {
            cv += __shfl_down_sync(0xffffffffu, cv, off);
            rv += __shfl_down_sync(0xffffffffu, rv, off);
            pv += __shfl_down_sync(0xffffffffu, pv, off);
        }
        if (lid == 0) {
            atomicAdd(&g_cls_sum[b], cv);
            atomicAdd(&g_reg_sum[b], rv);
            atomicAdd(&g_pos_cnt[b], pv);
        }
    }
}

__global__ void finalize_kernel(float* __restrict__ out) {
    if (threadIdx.x == 0) {
        float cm = 0.f, rm = 0.f;
        #pragma unroll
        for (int b = 0; b < NB; b++) {
            float d = fmaxf((float)g_pos_cnt[b], 1.f);
            cm += g_cls_sum[b] / d;
            rm += g_reg_sum[b] / (4.f * d);
        }
        cm /= (float)NB;
        rm /= (float)NB;
        out[0] = cm;
        out[1] = rm;
        out[2] = cm + rm;
    }
}

extern "C" void kernel_launch(void* const* d_in, const int* in_sizes, int n_in,
                              void* d_out, int out_size)
{
    const float* logits  = (const float*)d_in[0];   // (B,A,K)
    const float* regp    = (const float*)d_in[1];   // (B,A,4)
    const float* anchors = (const float*)d_in[2];   // (A,4)
    const float* boxes   = (const float*)d_in[3];   // (B,M,4)
    const int*   classes = (const int*)  d_in[4];   // (B,M)
    float* out = (float*)d_out;

    zero_kernel<<<1, 32>>>();
    dim3 grid(BPI, NB);
    retina_main_kernel<<<grid, TPB>>>(logits, regp, anchors, boxes, classes);
    finalize_kernel<<<1, 32>>>(out);
}

// round 2
// speedup vs baseline: 1.9892x; 1.9892x over previous
#include <cuda_runtime.h>
#include <cstdint>

#define NB 8
#define NA 49104
#define NM 50
#define NK 80
#define TPB 256
#define BPI ((NA + TPB - 1) / TPB)   // 192 blocks per image
#define NBLK (BPI * NB)

__device__ float    g_cls[NB];
__device__ float    g_reg[NB];
__device__ int      g_pos[NB];
__device__ unsigned g_ticket;

__device__ __forceinline__ float smooth_l1(float d) {
    d = fabsf(d);
    const float BETA = 1.0f / 9.0f;
    return (d <= BETA) ? (4.5f * d * d) : (d - 0.5f * BETA);
}

__global__ __launch_bounds__(TPB, 4)
void retina_fused_kernel(const float* __restrict__ logits,
                         const float* __restrict__ regp,
                         const float* __restrict__ anchors,
                         const float* __restrict__ boxes,
                         const int*   __restrict__ classes,
                         float* __restrict__ out)
{
    __shared__ float4 sbox[NM];
    __shared__ float  sarea[NM];
    __shared__ int    scls[NM];
    __shared__ float  sw[TPB];       // per-anchor focal weight (0 or -0.75*ln2)
    __shared__ float  sredf[8];
    __shared__ float  sredr[8];
    __shared__ int    sredi[8];
    __shared__ int    slast;

    const int b   = blockIdx.y;
    const int a0  = blockIdx.x * TPB;
    const int tid = threadIdx.x;

    if (tid < NM) {
        float4 bx = ((const float4*)boxes)[b * NM + tid];
        sbox[tid]  = bx;
        sarea[tid] = (bx.z - bx.x) * (bx.w - bx.y);
        scls[tid]  = classes[b * NM + tid];
    }
    __syncthreads();

    // ---------- phase 1: division-free IoU argmax + reg loss + pos focal correction ----------
    const int a = a0 + tid;
    float reg_partial = 0.f;
    float cls_partial = 0.f;
    int   pos_partial = 0;
    const float C_NEG = -0.75f * 0.69314718055994531f;  // -0.75*ln2

    float wgt = 0.f;
    if (a < NA) {
        float4 an = ((const float4*)anchors)[a];
        float areaA = (an.z - an.x) * (an.w - an.y);
        float bI = -1e30f, bU = 1.f;   // best iou = bI/bU
        int   bi = 0;
        #pragma unroll 10
        for (int j = 0; j < NM; j++) {
            float4 bx = sbox[j];
            float iw = fmaxf(fminf(an.z, bx.z) - fmaxf(an.x, bx.x), 0.f);
            float ih = fmaxf(fminf(an.w, bx.w) - fmaxf(an.y, bx.y), 0.f);
            float inter = iw * ih;
            float ua = fmaxf(areaA + sarea[j] - inter, 1e-8f);
            if (bx.x == -1.0f) inter = -ua;          // padded -> iou = -1
            if (inter * bU > bI * ua) { bI = inter; bU = ua; bi = j; }
        }
        bool pos = bI >= 0.5f * bU;
        bool neg = bI <  0.4f * bU;
        wgt = (pos | neg) ? C_NEG : 0.f;

        if (pos) {
            pos_partial = 1;
            // focal correction for the single target class
            int tc = scls[bi] - 1;
            float p = logits[((size_t)b * NA + a) * NK + tc];
            float om = 1.f - p;
            cls_partial = 0.25f * om * om * (-__logf(p))
                        - 0.75f * p * p * (-__logf(om));
            // regression loss
            float4 gb = sbox[bi];
            float aw = an.z - an.x, ah = an.w - an.y;
            float acx = an.x + 0.5f * aw, acy = an.y + 0.5f * ah;
            float gw0 = gb.z - gb.x, gh0 = gb.w - gb.y;
            float gcx = gb.x + 0.5f * gw0, gcy = gb.y + 0.5f * gh0;
            float gw = fmaxf(gw0, 1.f), gh = fmaxf(gh0, 1.f);
            float t0 = ((gcx - acx) / aw) * 10.f;
            float t1 = ((gcy - acy) / ah) * 10.f;
            float t2 = __logf(gw / aw) * 5.f;
            float t3 = __logf(gh / ah) * 5.f;
            float4 rp = ((const float4*)regp)[(size_t)b * NA + a];
            reg_partial = smooth_l1(t0 - rp.x) + smooth_l1(t1 - rp.y)
                        + smooth_l1(t2 - rp.z) + smooth_l1(t3 - rp.w);
        }
    }
    sw[tid] = wgt;
    __syncthreads();

    // ---------- phase 2: branch-free focal stream ----------
    const int na  = min(TPB, NA - a0);
    const int nf4 = na * (NK / 4);                 // float4 count
    const float4* lg4 = (const float4*)(logits + ((size_t)b * NA + a0) * NK);

    #pragma unroll 4
    for (int i = tid; i < nf4; i += TPB) {
        float4 q = lg4[i];
        int al = i / (NK / 4);                     // anchor-local index
        float s;
        s  = q.x * q.x * __log2f(1.f - q.x);
        s += q.y * q.y * __log2f(1.f - q.y);
        s += q.z * q.z * __log2f(1.f - q.z);
        s += q.w * q.w * __log2f(1.f - q.w);
        cls_partial = fmaf(sw[al], s, cls_partial);
    }

    // ---------- reduction ----------
    float cv = cls_partial, rv = reg_partial;
    int   pv = pos_partial;
    #pragma unroll
    for (int off = 16; off > 0; off >>= 1) {
        cv += __shfl_down_sync(0xffffffffu, cv, off);
        rv += __shfl_down_sync(0xffffffffu, rv, off);
        pv += __shfl_down_sync(0xffffffffu, pv, off);
    }
    int wid = tid >> 5, lid = tid & 31;
    if (lid == 0) { sredf[wid] = cv; sredr[wid] = rv; sredi[wid] = pv; }
    __syncthreads();
    if (wid == 0) {
        cv = (lid < 8) ? sredf[lid] : 0.f;
        rv = (lid < 8) ? sredr[lid] : 0.f;
        pv = (lid < 8) ? sredi[lid] : 0;
        #pragma unroll
        for (int off = 4; off > 0; off >>= 1) {
            cv += __shfl_down_sync(0xffffffffu, cv, off);
            rv += __shfl_down_sync(0xffffffffu, rv, off);
            pv += __shfl_down_sync(0xffffffffu, pv, off);
        }
        if (lid == 0) {
            atomicAdd(&g_cls[b], cv);
            atomicAdd(&g_reg[b], rv);
            atomicAdd(&g_pos[b], pv);
        }
    }

    // ---------- last-block finalize + self-reset ----------
    __threadfence();
    if (tid == 0) {
        unsigned t = atomicAdd(&g_ticket, 1u);
        slast = (t == (unsigned)(NBLK - 1));
    }
    __syncthreads();
    if (slast && tid == 0) {
        __threadfence();
        volatile float* vc = g_cls;
        volatile float* vr = g_reg;
        volatile int*   vp = g_pos;
        float cm = 0.f, rm = 0.f;
        #pragma unroll
        for (int i = 0; i < NB; i++) {
            float d = fmaxf((float)vp[i], 1.f);
            cm += vc[i] / d;
            rm += vr[i] / (4.f * d);
        }
        cm /= (float)NB;
        rm /= (float)NB;
        out[0] = cm;
        out[1] = rm;
        out[2] = cm + rm;
        #pragma unroll
        for (int i = 0; i < NB; i++) { g_cls[i] = 0.f; g_reg[i] = 0.f; g_pos[i] = 0; }
        g_ticket = 0u;
    }
}

extern "C" void kernel_launch(void* const* d_in, const int* in_sizes, int n_in,
                              void* d_out, int out_size)
{
    const float* logits  = (const float*)d_in[0];   // (B,A,K)
    const float* regp    = (const float*)d_in[1];   // (B,A,4)
    const float* anchors = (const float*)d_in[2];   // (A,4)
    const float* boxes   = (const float*)d_in[3];   // (B,M,4)
    const int*   classes = (const int*)  d_in[4];   // (B,M)
    float* out = (float*)d_out;

    dim3 grid(BPI, NB);
    retina_fused_kernel<<<grid, TPB>>>(logits, regp, anchors, boxes, classes, out);
}